// round 6
// baseline (speedup 1.0000x reference)
#include <cuda_runtime.h>
#include <cuda_fp16.h>
#include <stdint.h>

#define BB 2048
#define SS 128
#define DD 128
#define HH 256
#define GG 1024  // 4*H
#define NCTAS 256

// ---------------- device scratch (allocation-free) ----------------
__device__ float g_c1[BB * HH];
__device__ float g_c2[BB * HH];
__device__ __half g_h1[2][BB * HH];
__device__ __half g_h2[2][BB * HH];
__device__ __half g_din[BB * HH];
__device__ __half g_x[(size_t)BB * SS * DD];
__device__ float g_decout[(size_t)BB * SS * HH];  // 256 MB

__device__ __half g_wx[4][GG * HH];
__device__ __half g_wh[4][GG * HH];
__device__ float g_bias[4][GG];

__device__ unsigned g_bar_cnt;
__device__ unsigned g_bar_gen;

// ---------------- PTX helpers ----------------
__device__ __forceinline__ uint32_t smem_u32(const void* p) {
    uint32_t a;
    asm("{ .reg .u64 t; cvta.to.shared.u64 t, %1; cvt.u32.u64 %0, t; }" : "=r"(a) : "l"(p));
    return a;
}
#define CPA16(sm, g) asm volatile("cp.async.cg.shared.global [%0], [%1], 16;" :: "r"(sm), "l"(g) : "memory")
#define CP_COMMIT()  asm volatile("cp.async.commit_group;" ::: "memory")
#define CP_WAIT2()   asm volatile("cp.async.wait_group 2;" ::: "memory")
#define CP_WAIT1()   asm volatile("cp.async.wait_group 1;" ::: "memory")
#define CP_WAIT0()   asm volatile("cp.async.wait_group 0;" ::: "memory")
#define LDSM4(r0, r1, r2, r3, a) \
    asm volatile("ldmatrix.sync.aligned.m8n8.x4.shared.b16 {%0,%1,%2,%3}, [%4];" \
        : "=r"(r0), "=r"(r1), "=r"(r2), "=r"(r3) : "r"(a))
#define MMA16816(d, a, b0, b1) \
    asm volatile("mma.sync.aligned.m16n8k16.row.col.f32.f16.f16.f32 " \
        "{%0,%1,%2,%3},{%4,%5,%6,%7},{%8,%9},{%0,%1,%2,%3};" \
        : "+f"((d)[0]), "+f"((d)[1]), "+f"((d)[2]), "+f"((d)[3]) \
        : "r"((a)[0]), "r"((a)[1]), "r"((a)[2]), "r"((a)[3]), "r"(b0), "r"(b1))

__device__ __forceinline__ float sigf(float x) {
    return __fdividef(1.f, 1.f + __expf(-x));
}
__device__ __forceinline__ float tanhv(float x) {
    return 2.f * sigf(2.f * x) - 1.f;
}

// ---------------- software grid barrier (sense via generation counter) ------
// Safe: 256 CTAs <= 2/SM * 148 SMs guaranteed co-resident (launch_bounds(256,2)).
__device__ __forceinline__ void grid_bar() {
    __syncthreads();
    if (threadIdx.x == 0) {
        unsigned gen = *(volatile unsigned*)&g_bar_gen;
        __threadfence();
        unsigned t = atomicAdd(&g_bar_cnt, 1u);
        if (t == NCTAS - 1) {
            g_bar_cnt = 0;
            __threadfence();
            atomicExch(&g_bar_gen, gen + 1u);
        } else {
            while (*(volatile unsigned*)&g_bar_gen == gen) {}
        }
        __threadfence();
    }
    __syncthreads();
}

// ---------------- setup kernels ----------------
__global__ void conv_x(const float* __restrict__ x) {
    size_t i = (size_t)blockIdx.x * blockDim.x + threadIdx.x;
    if (i < (size_t)BB * SS * DD) g_x[i] = __float2half_rn(x[i]);
}

__global__ void setup_weights(
    const float* w0, const float* w1, const float* w2, const float* w3,
    const float* w4, const float* w5, const float* w6, const float* w7,
    const float* b0a, const float* b0b, const float* b1a, const float* b1b,
    const float* b2a, const float* b2b, const float* b3a, const float* b3b) {
    const int y = blockIdx.y;
    const int idx = blockIdx.x * blockDim.x + threadIdx.x;
    if (y < 8) {
        const int wsel = y >> 1, which = y & 1;
        const int K = (y == 0) ? DD : HH;
        if (idx >= GG * K) return;
        const float* srcs[8] = {w0, w1, w2, w3, w4, w5, w6, w7};
        const float* src = srcs[y];
        int row = idx / K;
        int k = idx - row * K;
        int n = row >> 2, g = row & 3;
        __half v = __float2half_rn(src[(g * HH + n) * K + k]);
        if (which) g_wh[wsel][idx] = v;
        else       g_wx[wsel][idx] = v;
    } else {
        if (idx >= 4 * GG) return;
        const int wsel = idx >> 10;
        const int r = idx & (GG - 1);
        const float* bihs[4] = {b0a, b1a, b2a, b3a};
        const float* bhhs[4] = {b0b, b1b, b2b, b3b};
        int n = r >> 2, g = r & 3;
        g_bias[wsel][r] = bihs[wsel][g * HH + n] + bhhs[wsel][g * HH + n];
    }
}

__global__ void zero_states() {
    int i = blockIdx.x * blockDim.x + threadIdx.x;
    if (i == 0) { g_bar_cnt = 0; }
    if (i < BB * HH) {
        __half z = __float2half(0.f);
        g_c1[i] = 0.f; g_c2[i] = 0.f;
        g_h1[0][i] = z; g_h1[1][i] = z;
        g_h2[0][i] = z; g_h2[1][i] = z;
    }
}

// ---------------- fused LSTM cell body (device function) ----------------
// CTA 64(M) x 128(N), 8 warps (2M x 4N), warp tile 32x32, K-chunk 32,
// 4-stage cp.async. SMEM/stage: A 64x80 + W 128x80 = 15360B; x4 = 61440B.
#define ROWB 80
#define A_BYTES 5120
#define BUF_STRIDE 15360

__device__ __forceinline__ void run_cell(
    const char* bA1, size_t ldA1b, int K1,
    const char* bA2, const char* bW1, const char* bW2,
    const float* __restrict__ bias, float* cbase, __half* hout, float* dbase,
    uint32_t smu, int tid, int lane, int m0, int n0, int wm, int wn,
    const uint32_t* aoff, const uint32_t* woff) {

    const int nk1c = K1 >> 5;
    const int ns = nk1c + (HH >> 5);

    float acc[2][4][4];
#pragma unroll
    for (int mt = 0; mt < 2; mt++)
#pragma unroll
        for (int j = 0; j < 4; j++)
#pragma unroll
            for (int r = 0; r < 4; r++) acc[mt][j][r] = 0.f;

    auto issue = [&](int cs, int buf) {
        const char *sA, *sW;
        size_t ldAb, ldWb, kb;
        if (cs < nk1c) {
            kb = (size_t)cs * 64;
            ldAb = ldA1b; ldWb = (size_t)K1 * 2;
            sA = bA1 + kb; sW = bW1 + kb;
        } else {
            kb = (size_t)(cs - nk1c) * 64;
            ldAb = HH * 2; ldWb = HH * 2;
            sA = bA2 + kb; sW = bW2 + kb;
        }
        const uint32_t sb = smu + buf * BUF_STRIDE;
        {
            const int row = tid >> 2;
            const uint32_t cb = (uint32_t)(tid & 3) * 16;
            CPA16(sb + (uint32_t)row * ROWB + cb, sA + (size_t)row * ldAb + cb);
        }
#pragma unroll
        for (int it = 0; it < 2; it++) {
            const int f = tid + (it << 8);
            const int row = f >> 2;
            const uint32_t cb = (uint32_t)(f & 3) * 16;
            CPA16(sb + A_BYTES + (uint32_t)row * ROWB + cb, sW + (size_t)row * ldWb + cb);
        }
        CP_COMMIT();
    };

    issue(0, 0);
    issue(1, 1);
    issue(2, 2);

    for (int s = 0; s < ns; s++) {
        if (s + 2 < ns)      CP_WAIT2();
        else if (s + 1 < ns) CP_WAIT1();
        else                 CP_WAIT0();
        __syncthreads();

        const uint32_t base = smu + (s & 3) * BUF_STRIDE;
#pragma unroll
        for (int ks = 0; ks < 2; ks++) {
            uint32_t a[2][4];
#pragma unroll
            for (int mt = 0; mt < 2; mt++)
                LDSM4(a[mt][0], a[mt][1], a[mt][2], a[mt][3], base + aoff[mt] + ks * 32);
            uint32_t w[8];
#pragma unroll
            for (int j2 = 0; j2 < 2; j2++) {
                const uint32_t wd = base + A_BYTES + woff[j2] + ks * 32;
                LDSM4(w[4*j2+0], w[4*j2+1], w[4*j2+2], w[4*j2+3], wd);
            }
#pragma unroll
            for (int mt = 0; mt < 2; mt++)
#pragma unroll
                for (int j = 0; j < 4; j++)
                    MMA16816(acc[mt][j], a[mt], w[2*j], w[2*j+1]);
        }
        if (s + 3 < ns) issue(s + 3, (s + 3) & 3);
    }

    // epilogue: shfl.xor(1) pairs (i,f)/(g,o) halves -> full unit per thread
    const int q = lane & 3, p = q & 1, g = lane >> 2;
#pragma unroll
    for (int mt = 0; mt < 2; mt++) {
#pragma unroll
        for (int j = 0; j < 4; j++) {
            float c0 = acc[mt][j][0], c1 = acc[mt][j][1];
            float c2 = acc[mt][j][2], c3 = acc[mt][j][3];
            float e0 = __shfl_xor_sync(0xffffffffu, c0, 1);
            float e1 = __shfl_xor_sync(0xffffffffu, c1, 1);
            float e2 = __shfl_xor_sync(0xffffffffu, c2, 1);
            float e3 = __shfl_xor_sync(0xffffffffu, c3, 1);
            const int row = m0 + wm + mt * 16 + g + (p ? 8 : 0);
            const int col = n0 + wn + j * 8 + (q >> 1) * 4;
            float zi, zf, zg, zo;
            if (!p) { zi = c0; zf = c1; zg = e0; zo = e1; }
            else    { zi = e2; zf = e3; zg = c2; zo = c3; }
            zi += bias[col];     zf += bias[col + 1];
            zg += bias[col + 2]; zo += bias[col + 3];
            const int un = col >> 2;
            const size_t si = (size_t)row * HH + un;
            float cold = cbase[si];
            float ig = sigf(zi), fg = sigf(zf), og = sigf(zo);
            float gt = tanhv(zg);
            float cn = fg * cold + ig * gt;
            float hn = og * tanhv(cn);
            cbase[si] = cn;
            hout[si] = __float2half_rn(hn);
            if (dbase)
                dbase[(size_t)row * (SS * HH) + un] = hn;
        }
    }
}

// ---------------- persistent whole-recurrence kernel ----------------
__global__ __launch_bounds__(256, 2)
void lstm_persist() {
    extern __shared__ char sm[];
    const uint32_t smu = smem_u32(sm);
    const int tid = threadIdx.x;
    const int lane = tid & 31, wid = tid >> 5;
    const int bid = blockIdx.x;
    const int n0 = (bid & 7) * 128;
    const int m0 = (bid >> 3) * 64;
    const int wm = (wid & 1) * 32;
    const int wn = (wid >> 1) * 32;

    uint32_t aoff[2], woff[2];
#pragma unroll
    for (int mt = 0; mt < 2; mt++)
        aoff[mt] = (uint32_t)(wm + mt * 16 + (lane & 15)) * ROWB + ((lane >> 4) * 16);
#pragma unroll
    for (int j2 = 0; j2 < 2; j2++)
        woff[j2] = (uint32_t)(wn + (j2 * 2 + (lane >> 4)) * 8 + (lane & 7)) * ROWB
                 + (((lane >> 3) & 1) * 16);

    // ---- encoder: 2*SS cells ----
    for (int s = 0; s < 2 * SS; s++) {
        const int t = s >> 1, p = t & 1;
        const char *bA1, *bA2, *bW1, *bW2;
        size_t ldA1b; int K1, ws;
        float* cb; __half* ho;
        if ((s & 1) == 0) {
            ldA1b = (size_t)SS * DD * 2;
            bA1 = (const char*)g_x + ((size_t)m0 * SS * DD + (size_t)t * DD) * 2;
            K1 = DD; ws = 0;
            bA2 = (const char*)g_h1[p] + (size_t)m0 * HH * 2;
            cb = g_c1; ho = g_h1[1 - p];
        } else {
            ldA1b = HH * 2;
            bA1 = (const char*)g_h1[1 - p] + (size_t)m0 * HH * 2;
            K1 = HH; ws = 1;
            bA2 = (const char*)g_h2[p] + (size_t)m0 * HH * 2;
            cb = g_c2; ho = g_h2[1 - p];
        }
        bW1 = (const char*)g_wx[ws] + (size_t)n0 * K1 * 2;
        bW2 = (const char*)g_wh[ws] + (size_t)n0 * HH * 2;
        run_cell(bA1, ldA1b, K1, bA2, bW1, bW2, g_bias[ws], cb, ho, nullptr,
                 smu, tid, lane, m0, n0, wm, wn, aoff, woff);
        grid_bar();
    }

    // ---- reset: din = encoded (h2[0]); zero states ----
    {
        const int gt = bid * 256 + tid;
        for (int i = gt; i < BB * HH; i += NCTAS * 256) {
            __half v = g_h2[0][i];
            __half z = __float2half(0.f);
            g_din[i] = v;
            g_h1[0][i] = z; g_h1[1][i] = z;
            g_h2[0][i] = z; g_h2[1][i] = z;
            g_c1[i] = 0.f; g_c2[i] = 0.f;
        }
        grid_bar();
    }

    // ---- decoder: 2*SS cells ----
    for (int s = 0; s < 2 * SS; s++) {
        const int t = s >> 1, p = t & 1;
        const char *bA1, *bA2, *bW1, *bW2;
        int ws;
        float* cb; __half* ho; float* db = nullptr;
        if ((s & 1) == 0) {
            const __half* a1src = (t == 0) ? g_din : g_h2[p];
            bA1 = (const char*)a1src + (size_t)m0 * HH * 2;
            ws = 2;
            bA2 = (const char*)g_h1[p] + (size_t)m0 * HH * 2;
            cb = g_c1; ho = g_h1[1 - p];
        } else {
            bA1 = (const char*)g_h1[1 - p] + (size_t)m0 * HH * 2;
            ws = 3;
            bA2 = (const char*)g_h2[p] + (size_t)m0 * HH * 2;
            cb = g_c2; ho = g_h2[1 - p];
            db = g_decout + (size_t)t * HH;
        }
        bW1 = (const char*)g_wx[ws] + (size_t)n0 * HH * 2;
        bW2 = (const char*)g_wh[ws] + (size_t)n0 * HH * 2;
        run_cell(bA1, HH * 2, HH, bA2, bW1, bW2, g_bias[ws], cb, ho, db,
                 smu, tid, lane, m0, n0, wm, wn, aoff, woff);
        grid_bar();
    }
}

// ---------------- output projection: out = decout @ Wout^T + bout ----------
__global__ __launch_bounds__(256, 1)
void out_proj(const float* __restrict__ W, const float* __restrict__ bout,
              float* __restrict__ out) {
    __shared__ float As[2][16][132];
    __shared__ float Bs[2][16][132];

    const int tid = threadIdx.x;
    const int tx = tid & 15, ty = tid >> 4;
    const int m0 = blockIdx.y * 128;

    const int arow = tid >> 1;
    const int acol = (tid & 1) << 3;
    const int ntiles = HH >> 4;  // 16

    const float* a0row = g_decout + (size_t)(m0 + arow) * HH + acol;
    const float* w0row = W + (size_t)arow * HH + acol;

    float acc[8][8];
#pragma unroll
    for (int i = 0; i < 8; i++)
#pragma unroll
        for (int j = 0; j < 8; j++) acc[i][j] = 0.f;

    {
        float4 ra0 = *(const float4*)a0row;
        float4 ra1 = *(const float4*)(a0row + 4);
        float4 rb0 = *(const float4*)w0row;
        float4 rb1 = *(const float4*)(w0row + 4);
        float* sa = &As[0][acol][arow];
        float* sb = &Bs[0][acol][arow];
        sa[0*132]=ra0.x; sa[1*132]=ra0.y; sa[2*132]=ra0.z; sa[3*132]=ra0.w;
        sa[4*132]=ra1.x; sa[5*132]=ra1.y; sa[6*132]=ra1.z; sa[7*132]=ra1.w;
        sb[0*132]=rb0.x; sb[1*132]=rb0.y; sb[2*132]=rb0.z; sb[3*132]=rb0.w;
        sb[4*132]=rb1.x; sb[5*132]=rb1.y; sb[6*132]=rb1.z; sb[7*132]=rb1.w;
    }
    __syncthreads();

    for (int t = 0; t < ntiles; t++) {
        const int cur = t & 1;
        const bool more = (t + 1 < ntiles);
        float4 ra0, ra1, rb0, rb1;
        if (more) {
            const float* ap = a0row + (t + 1) * 16;
            const float* wp = w0row + (t + 1) * 16;
            ra0 = *(const float4*)ap; ra1 = *(const float4*)(ap + 4);
            rb0 = *(const float4*)wp; rb1 = *(const float4*)(wp + 4);
        }
#pragma unroll
        for (int k = 0; k < 16; k++) {
            const float* as = &As[cur][k][0];
            const float* bs = &Bs[cur][k][0];
            float4 a0 = *(const float4*)(as + ty * 8);
            float4 a1 = *(const float4*)(as + ty * 8 + 4);
            float4 b0 = *(const float4*)(bs + tx * 8);
            float4 b1 = *(const float4*)(bs + tx * 8 + 4);
            float av[8] = {a0.x, a0.y, a0.z, a0.w, a1.x, a1.y, a1.z, a1.w};
            float bv[8] = {b0.x, b0.y, b0.z, b0.w, b1.x, b1.y, b1.z, b1.w};
#pragma unroll
            for (int i = 0; i < 8; i++)
#pragma unroll
                for (int j = 0; j < 8; j++) acc[i][j] += av[i] * bv[j];
        }
        if (more) {
            const int nxt = cur ^ 1;
            float* sa = &As[nxt][acol][arow];
            float* sb = &Bs[nxt][acol][arow];
            sa[0*132]=ra0.x; sa[1*132]=ra0.y; sa[2*132]=ra0.z; sa[3*132]=ra0.w;
            sa[4*132]=ra1.x; sa[5*132]=ra1.y; sa[6*132]=ra1.z; sa[7*132]=ra1.w;
            sb[0*132]=rb0.x; sb[1*132]=rb0.y; sb[2*132]=rb0.z; sb[3*132]=rb0.w;
            sb[4*132]=rb1.x; sb[5*132]=rb1.y; sb[6*132]=rb1.z; sb[7*132]=rb1.w;
        }
        __syncthreads();
    }

#pragma unroll
    for (int i = 0; i < 8; i++) {
        const int m = m0 + ty * 8 + i;
#pragma unroll
        for (int j = 0; j < 8; j++) {
            const int col = tx * 8 + j;
            out[(size_t)m * DD + col] = acc[i][j] + bout[col];
        }
    }
}

// ---------------- host-side orchestration ----------------------------------
extern "C" void kernel_launch(void* const* d_in, const int* in_sizes, int n_in,
                              void* d_out, int out_size) {
    (void)in_sizes; (void)n_in; (void)out_size;
    const float* x = (const float*)d_in[0];

    static const int SMEM_DYN = 4 * BUF_STRIDE;  // 61440
    cudaFuncSetAttribute(lstm_persist, cudaFuncAttributeMaxDynamicSharedMemorySize, SMEM_DYN);

    conv_x<<<(int)(((size_t)BB * SS * DD + 255) / 256), 256>>>(x);
    setup_weights<<<dim3((GG * HH + 255) / 256, 9), 256>>>(
        (const float*)d_in[1], (const float*)d_in[2],
        (const float*)d_in[5], (const float*)d_in[6],
        (const float*)d_in[9], (const float*)d_in[10],
        (const float*)d_in[13], (const float*)d_in[14],
        (const float*)d_in[3], (const float*)d_in[4],
        (const float*)d_in[7], (const float*)d_in[8],
        (const float*)d_in[11], (const float*)d_in[12],
        (const float*)d_in[15], (const float*)d_in[16]);
    zero_states<<<(BB * HH + 255) / 256, 256>>>();

    // whole recurrence in ONE persistent kernel (256 CTAs, all co-resident)
    lstm_persist<<<NCTAS, 256, SMEM_DYN>>>();

    // output projection
    out_proj<<<dim3(1, (BB * SS) / 128), 256>>>((const float*)d_in[17],
                                                (const float*)d_in[18],
                                                (float*)d_out);
}

// round 7
// speedup vs baseline: 1.3827x; 1.3827x over previous
#include <cuda_runtime.h>
#include <cuda_fp16.h>
#include <stdint.h>

#define BB 2048
#define SS 128
#define DD 128
#define HH 256
#define GG 1024  // 4*H
#define NCELLS 512

// ---------------- device scratch (allocation-free) ----------------
__device__ float g_c1[BB * HH];
__device__ float g_c2[BB * HH];
__device__ __half g_h1[2][BB * HH];
__device__ __half g_h2[2][BB * HH];
__device__ __half g_din[BB * HH];
__device__ __half g_x[(size_t)BB * SS * DD];
__device__ float g_decout[(size_t)BB * SS * HH];  // 256 MB

__device__ __half g_wx[4][GG * HH];
__device__ __half g_wh[4][GG * HH];
__device__ float g_bias[4][GG];

__device__ unsigned g_grpcnt[32];

// per-cell descriptors (filled once per launch by fill_desc)
struct CellDesc {
    const __half* A1;
    const __half* A2;
    const __half* W1;
    const __half* W2;
    const float* bias;
    float* c;
    __half* h;
    float* dout;     // nullptr unless decoder layer-2
    unsigned ldA1b;  // bytes
    int K1;
};
__device__ CellDesc g_desc[NCELLS];

// ---------------- PTX helpers ----------------
__device__ __forceinline__ uint32_t smem_u32(const void* p) {
    uint32_t a;
    asm("{ .reg .u64 t; cvta.to.shared.u64 t, %1; cvt.u32.u64 %0, t; }" : "=r"(a) : "l"(p));
    return a;
}
#define CPA16(sm, g) asm volatile("cp.async.cg.shared.global [%0], [%1], 16;" :: "r"(sm), "l"(g) : "memory")
#define CP_COMMIT()  asm volatile("cp.async.commit_group;" ::: "memory")
#define CP_WAIT2()   asm volatile("cp.async.wait_group 2;" ::: "memory")
#define CP_WAIT1()   asm volatile("cp.async.wait_group 1;" ::: "memory")
#define CP_WAIT0()   asm volatile("cp.async.wait_group 0;" ::: "memory")
#define LDSM4(r0, r1, r2, r3, a) \
    asm volatile("ldmatrix.sync.aligned.m8n8.x4.shared.b16 {%0,%1,%2,%3}, [%4];" \
        : "=r"(r0), "=r"(r1), "=r"(r2), "=r"(r3) : "r"(a))
#define MMA16816(d, a, b0, b1) \
    asm volatile("mma.sync.aligned.m16n8k16.row.col.f32.f16.f16.f32 " \
        "{%0,%1,%2,%3},{%4,%5,%6,%7},{%8,%9},{%0,%1,%2,%3};" \
        : "+f"((d)[0]), "+f"((d)[1]), "+f"((d)[2]), "+f"((d)[3]) \
        : "r"((a)[0]), "r"((a)[1]), "r"((a)[2]), "r"((a)[3]), "r"(b0), "r"(b1))

__device__ __forceinline__ float sigf(float x) {
    return __fdividef(1.f, 1.f + __expf(-x));
}
__device__ __forceinline__ float tanhv(float x) {
    return 2.f * sigf(2.f * x) - 1.f;
}

// ---------------- per-m-lane barrier (8 CTAs share one lane) ----------------
__device__ __forceinline__ void lane_bar(int grp, unsigned target) {
    __syncthreads();
    if (threadIdx.x == 0) {
        __threadfence();
        atomicAdd(&g_grpcnt[grp], 1u);
        while (atomicAdd(&g_grpcnt[grp], 0u) < target) {}
        __threadfence();
    }
    __syncthreads();
}

// ---------------- setup kernels ----------------
__global__ void conv_x(const float* __restrict__ x) {
    size_t i = (size_t)blockIdx.x * blockDim.x + threadIdx.x;
    if (i < (size_t)BB * SS * DD) g_x[i] = __float2half_rn(x[i]);
}

__global__ void setup_weights(
    const float* w0, const float* w1, const float* w2, const float* w3,
    const float* w4, const float* w5, const float* w6, const float* w7,
    const float* b0a, const float* b0b, const float* b1a, const float* b1b,
    const float* b2a, const float* b2b, const float* b3a, const float* b3b) {
    const int y = blockIdx.y;
    const int idx = blockIdx.x * blockDim.x + threadIdx.x;
    if (y < 8) {
        const int wsel = y >> 1, which = y & 1;
        const int K = (y == 0) ? DD : HH;
        if (idx >= GG * K) return;
        const float* srcs[8] = {w0, w1, w2, w3, w4, w5, w6, w7};
        const float* src = srcs[y];
        int row = idx / K;
        int k = idx - row * K;
        int n = row >> 2, g = row & 3;
        __half v = __float2half_rn(src[(g * HH + n) * K + k]);
        if (which) g_wh[wsel][idx] = v;
        else       g_wx[wsel][idx] = v;
    } else {
        if (idx >= 4 * GG) return;
        const int wsel = idx >> 10;
        const int r = idx & (GG - 1);
        const float* bihs[4] = {b0a, b1a, b2a, b3a};
        const float* bhhs[4] = {b0b, b1b, b2b, b3b};
        int n = r >> 2, g = r & 3;
        g_bias[wsel][r] = bihs[wsel][g * HH + n] + bhhs[wsel][g * HH + n];
    }
}

__global__ void zero_states() {
    int i = blockIdx.x * blockDim.x + threadIdx.x;
    if (i < 32) g_grpcnt[i] = 0u;
    if (i < BB * HH) {
        __half z = __float2half(0.f);
        g_c1[i] = 0.f; g_c2[i] = 0.f;
        g_h1[0][i] = z; g_h1[1][i] = z;
        g_h2[0][i] = z; g_h2[1][i] = z;
    }
}

__global__ void fill_desc() {
    int s = blockIdx.x * blockDim.x + threadIdx.x;
    if (s >= NCELLS) return;
    CellDesc d;
    d.dout = nullptr;
    if (s < 2 * SS) {                       // encoder
        int t = s >> 1, p = t & 1;
        if ((s & 1) == 0) {                 // layer 0
            d.A1 = g_x + (size_t)t * DD; d.ldA1b = SS * DD * 2; d.K1 = DD;
            d.A2 = g_h1[p]; d.W1 = g_wx[0]; d.W2 = g_wh[0]; d.bias = g_bias[0];
            d.c = g_c1; d.h = g_h1[1 - p];
        } else {                            // layer 1
            d.A1 = g_h1[1 - p]; d.ldA1b = HH * 2; d.K1 = HH;
            d.A2 = g_h2[p]; d.W1 = g_wx[1]; d.W2 = g_wh[1]; d.bias = g_bias[1];
            d.c = g_c2; d.h = g_h2[1 - p];
        }
    } else {                                // decoder
        int t = (s - 2 * SS) >> 1, p = t & 1;
        if ((s & 1) == 0) {                 // layer 0
            d.A1 = (t == 0) ? g_din : g_h2[p]; d.ldA1b = HH * 2; d.K1 = HH;
            d.A2 = g_h1[p]; d.W1 = g_wx[2]; d.W2 = g_wh[2]; d.bias = g_bias[2];
            d.c = g_c1; d.h = g_h1[1 - p];
        } else {                            // layer 1
            d.A1 = g_h1[1 - p]; d.ldA1b = HH * 2; d.K1 = HH;
            d.A2 = g_h2[p]; d.W1 = g_wx[3]; d.W2 = g_wh[3]; d.bias = g_bias[3];
            d.c = g_c2; d.h = g_h2[1 - p];
            d.dout = g_decout + (size_t)t * HH;
        }
    }
    g_desc[s] = d;
}

// ---------------- fused LSTM cell body ----------------
// CTA 64(M) x 128(N), 8 warps (2M x 4N), warp tile 32x32, K-chunk 32,
// 4-stage cp.async. SMEM/stage: A 64x80 + W 128x80 = 15360B; x4 = 61440B.
#define ROWB 80
#define A_BYTES 5120
#define BUF_STRIDE 15360

__device__ __forceinline__ void run_cell(
    const char* bA1, unsigned ldA1b, int K1,
    const char* bA2, const char* bW1, const char* bW2,
    const float* __restrict__ bias, float* cbase, __half* hout, float* dbase,
    uint32_t smu, int tid, int lane, int m0, int n0, int wm, int wn,
    const uint32_t* aoff, const uint32_t* woff) {

    const int nk1c = K1 >> 5;
    const int ns = nk1c + (HH >> 5);

    float acc[2][4][4];
#pragma unroll
    for (int mt = 0; mt < 2; mt++)
#pragma unroll
        for (int j = 0; j < 4; j++)
#pragma unroll
            for (int r = 0; r < 4; r++) acc[mt][j][r] = 0.f;

    auto issue = [&](int cs, int buf) {
        const char *sA, *sW;
        size_t ldAb, ldWb, kb;
        if (cs < nk1c) {
            kb = (size_t)cs * 64;
            ldAb = ldA1b; ldWb = (size_t)K1 * 2;
            sA = bA1 + kb; sW = bW1 + kb;
        } else {
            kb = (size_t)(cs - nk1c) * 64;
            ldAb = HH * 2; ldWb = HH * 2;
            sA = bA2 + kb; sW = bW2 + kb;
        }
        const uint32_t sb = smu + buf * BUF_STRIDE;
        {
            const int row = tid >> 2;
            const uint32_t cb = (uint32_t)(tid & 3) * 16;
            CPA16(sb + (uint32_t)row * ROWB + cb, sA + (size_t)row * ldAb + cb);
        }
#pragma unroll
        for (int it = 0; it < 2; it++) {
            const int f = tid + (it << 8);
            const int row = f >> 2;
            const uint32_t cb = (uint32_t)(f & 3) * 16;
            CPA16(sb + A_BYTES + (uint32_t)row * ROWB + cb, sW + (size_t)row * ldWb + cb);
        }
        CP_COMMIT();
    };

    issue(0, 0);
    issue(1, 1);
    issue(2, 2);

    for (int s = 0; s < ns; s++) {
        if (s + 2 < ns)      CP_WAIT2();
        else if (s + 1 < ns) CP_WAIT1();
        else                 CP_WAIT0();
        __syncthreads();

        const uint32_t base = smu + (s & 3) * BUF_STRIDE;
#pragma unroll
        for (int ks = 0; ks < 2; ks++) {
            uint32_t a[2][4];
#pragma unroll
            for (int mt = 0; mt < 2; mt++)
                LDSM4(a[mt][0], a[mt][1], a[mt][2], a[mt][3], base + aoff[mt] + ks * 32);
            uint32_t w[8];
#pragma unroll
            for (int j2 = 0; j2 < 2; j2++) {
                const uint32_t wd = base + A_BYTES + woff[j2] + ks * 32;
                LDSM4(w[4*j2+0], w[4*j2+1], w[4*j2+2], w[4*j2+3], wd);
            }
#pragma unroll
            for (int mt = 0; mt < 2; mt++)
#pragma unroll
                for (int j = 0; j < 4; j++)
                    MMA16816(acc[mt][j], a[mt], w[2*j], w[2*j+1]);
        }
        if (s + 3 < ns) issue(s + 3, (s + 3) & 3);
    }

    // epilogue: shfl.xor(1) pairs (i,f)/(g,o) halves -> full unit per thread
    const int q = lane & 3, p = q & 1, g = lane >> 2;
#pragma unroll
    for (int mt = 0; mt < 2; mt++) {
#pragma unroll
        for (int j = 0; j < 4; j++) {
            float c0 = acc[mt][j][0], c1 = acc[mt][j][1];
            float c2 = acc[mt][j][2], c3 = acc[mt][j][3];
            float e0 = __shfl_xor_sync(0xffffffffu, c0, 1);
            float e1 = __shfl_xor_sync(0xffffffffu, c1, 1);
            float e2 = __shfl_xor_sync(0xffffffffu, c2, 1);
            float e3 = __shfl_xor_sync(0xffffffffu, c3, 1);
            const int row = m0 + wm + mt * 16 + g + (p ? 8 : 0);
            const int col = n0 + wn + j * 8 + (q >> 1) * 4;
            float zi, zf, zg, zo;
            if (!p) { zi = c0; zf = c1; zg = e0; zo = e1; }
            else    { zi = e2; zf = e3; zg = c2; zo = c3; }
            zi += bias[col];     zf += bias[col + 1];
            zg += bias[col + 2]; zo += bias[col + 3];
            const int un = col >> 2;
            const size_t si = (size_t)row * HH + un;
            float cold = cbase[si];
            float ig = sigf(zi), fg = sigf(zf), og = sigf(zo);
            float gt = tanhv(zg);
            float cn = fg * cold + ig * gt;
            float hn = og * tanhv(cn);
            cbase[si] = cn;
            hout[si] = __float2half_rn(hn);
            if (dbase)
                dbase[(size_t)row * (SS * HH) + un] = hn;
        }
    }
}

// ---------------- persistent whole-recurrence kernel ----------------
__global__ __launch_bounds__(256, 2)
void lstm_persist() {
    extern __shared__ char sm[];
    const uint32_t smu = smem_u32(sm);
    const int tid = threadIdx.x;
    const int lane = tid & 31, wid = tid >> 5;
    const int n0 = blockIdx.x * 128;      // 8 N-tiles
    const int grp = blockIdx.y;           // 32 m-lanes
    const int m0 = grp * 64;
    const int wm = (wid & 1) * 32;
    const int wn = (wid >> 1) * 32;

    uint32_t aoff[2], woff[2];
#pragma unroll
    for (int mt = 0; mt < 2; mt++)
        aoff[mt] = (uint32_t)(wm + mt * 16 + (lane & 15)) * ROWB + ((lane >> 4) * 16);
#pragma unroll
    for (int j2 = 0; j2 < 2; j2++)
        woff[j2] = (uint32_t)(wn + (j2 * 2 + (lane >> 4)) * 8 + (lane & 7)) * ROWB
                 + (((lane >> 3) & 1) * 16);

    unsigned epoch = 0;

    for (int s = 0; s < NCELLS; s++) {
        CellDesc d = g_desc[s];
        const char* bA1 = (const char*)d.A1 + (size_t)m0 * d.ldA1b;
        const char* bA2 = (const char*)d.A2 + (size_t)m0 * HH * 2;
        const char* bW1 = (const char*)d.W1 + (size_t)n0 * d.K1 * 2;
        const char* bW2 = (const char*)d.W2 + (size_t)n0 * HH * 2;
        run_cell(bA1, d.ldA1b, d.K1, bA2, bW1, bW2, d.bias, d.c, d.h, d.dout,
                 smu, tid, lane, m0, n0, wm, wn, aoff, woff);
        lane_bar(grp, 8u * (++epoch));

        if (s == 2 * SS - 1) {
            // encoder -> decoder reset, within this m-lane's slice only:
            // rows [m0, m0+64) x units [n0/4, n0/4+32)
            const int un0 = n0 >> 2;
            for (int i = tid; i < 64 * 32; i += 256) {
                const int r = m0 + (i >> 5);
                const int u = un0 + (i & 31);
                const size_t si = (size_t)r * HH + u;
                __half v = g_h2[0][si];
                __half z = __float2half(0.f);
                g_din[si] = v;
                g_h1[0][si] = z; g_h1[1][si] = z;
                g_h2[0][si] = z; g_h2[1][si] = z;
                g_c1[si] = 0.f;  g_c2[si] = 0.f;
            }
            lane_bar(grp, 8u * (++epoch));
        }
    }
}

// ---------------- output projection: out = decout @ Wout^T + bout ----------
__global__ __launch_bounds__(256, 1)
void out_proj(const float* __restrict__ W, const float* __restrict__ bout,
              float* __restrict__ out) {
    __shared__ float As[2][16][132];
    __shared__ float Bs[2][16][132];

    const int tid = threadIdx.x;
    const int tx = tid & 15, ty = tid >> 4;
    const int m0 = blockIdx.y * 128;

    const int arow = tid >> 1;
    const int acol = (tid & 1) << 3;
    const int ntiles = HH >> 4;  // 16

    const float* a0row = g_decout + (size_t)(m0 + arow) * HH + acol;
    const float* w0row = W + (size_t)arow * HH + acol;

    float acc[8][8];
#pragma unroll
    for (int i = 0; i < 8; i++)
#pragma unroll
        for (int j = 0; j < 8; j++) acc[i][j] = 0.f;

    {
        float4 ra0 = *(const float4*)a0row;
        float4 ra1 = *(const float4*)(a0row + 4);
        float4 rb0 = *(const float4*)w0row;
        float4 rb1 = *(const float4*)(w0row + 4);
        float* sa = &As[0][acol][arow];
        float* sb = &Bs[0][acol][arow];
        sa[0*132]=ra0.x; sa[1*132]=ra0.y; sa[2*132]=ra0.z; sa[3*132]=ra0.w;
        sa[4*132]=ra1.x; sa[5*132]=ra1.y; sa[6*132]=ra1.z; sa[7*132]=ra1.w;
        sb[0*132]=rb0.x; sb[1*132]=rb0.y; sb[2*132]=rb0.z; sb[3*132]=rb0.w;
        sb[4*132]=rb1.x; sb[5*132]=rb1.y; sb[6*132]=rb1.z; sb[7*132]=rb1.w;
    }
    __syncthreads();

    for (int t = 0; t < ntiles; t++) {
        const int cur = t & 1;
        const bool more = (t + 1 < ntiles);
        float4 ra0, ra1, rb0, rb1;
        if (more) {
            const float* ap = a0row + (t + 1) * 16;
            const float* wp = w0row + (t + 1) * 16;
            ra0 = *(const float4*)ap; ra1 = *(const float4*)(ap + 4);
            rb0 = *(const float4*)wp; rb1 = *(const float4*)(wp + 4);
        }
#pragma unroll
        for (int k = 0; k < 16; k++) {
            const float* as = &As[cur][k][0];
            const float* bs = &Bs[cur][k][0];
            float4 a0 = *(const float4*)(as + ty * 8);
            float4 a1 = *(const float4*)(as + ty * 8 + 4);
            float4 b0 = *(const float4*)(bs + tx * 8);
            float4 b1 = *(const float4*)(bs + tx * 8 + 4);
            float av[8] = {a0.x, a0.y, a0.z, a0.w, a1.x, a1.y, a1.z, a1.w};
            float bv[8] = {b0.x, b0.y, b0.z, b0.w, b1.x, b1.y, b1.z, b1.w};
#pragma unroll
            for (int i = 0; i < 8; i++)
#pragma unroll
                for (int j = 0; j < 8; j++) acc[i][j] += av[i] * bv[j];
        }
        if (more) {
            const int nxt = cur ^ 1;
            float* sa = &As[nxt][acol][arow];
            float* sb = &Bs[nxt][acol][arow];
            sa[0*132]=ra0.x; sa[1*132]=ra0.y; sa[2*132]=ra0.z; sa[3*132]=ra0.w;
            sa[4*132]=ra1.x; sa[5*132]=ra1.y; sa[6*132]=ra1.z; sa[7*132]=ra1.w;
            sb[0*132]=rb0.x; sb[1*132]=rb0.y; sb[2*132]=rb0.z; sb[3*132]=rb0.w;
            sb[4*132]=rb1.x; sb[5*132]=rb1.y; sb[6*132]=rb1.z; sb[7*132]=rb1.w;
        }
        __syncthreads();
    }

#pragma unroll
    for (int i = 0; i < 8; i++) {
        const int m = m0 + ty * 8 + i;
#pragma unroll
        for (int j = 0; j < 8; j++) {
            const int col = tx * 8 + j;
            out[(size_t)m * DD + col] = acc[i][j] + bout[col];
        }
    }
}

// ---------------- host-side orchestration ----------------------------------
extern "C" void kernel_launch(void* const* d_in, const int* in_sizes, int n_in,
                              void* d_out, int out_size) {
    (void)in_sizes; (void)n_in; (void)out_size;
    const float* x = (const float*)d_in[0];

    static const int SMEM_DYN = 4 * BUF_STRIDE;  // 61440
    cudaFuncSetAttribute(lstm_persist, cudaFuncAttributeMaxDynamicSharedMemorySize, SMEM_DYN);

    conv_x<<<(int)(((size_t)BB * SS * DD + 255) / 256), 256>>>(x);
    setup_weights<<<dim3((GG * HH + 255) / 256, 9), 256>>>(
        (const float*)d_in[1], (const float*)d_in[2],
        (const float*)d_in[5], (const float*)d_in[6],
        (const float*)d_in[9], (const float*)d_in[10],
        (const float*)d_in[13], (const float*)d_in[14],
        (const float*)d_in[3], (const float*)d_in[4],
        (const float*)d_in[7], (const float*)d_in[8],
        (const float*)d_in[11], (const float*)d_in[12],
        (const float*)d_in[15], (const float*)d_in[16]);
    zero_states<<<(BB * HH + 255) / 256, 256>>>();
    fill_desc<<<2, 256>>>();

    // whole recurrence in one persistent kernel; 32 independent m-lane barriers
    lstm_persist<<<dim3(8, 32), 256, SMEM_DYN>>>();

    out_proj<<<dim3(1, (BB * SS) / 128), 256>>>((const float*)d_in[17],
                                                (const float*)d_in[18],
                                                (float*)d_out);
}

// round 8
// speedup vs baseline: 1.5156x; 1.0961x over previous
#include <cuda_runtime.h>
#include <cuda_fp16.h>
#include <stdint.h>

#define BB 2048
#define SS 128
#define DD 128
#define HH 256
#define GG 1024
#define NCELLS 512
#define LANES 16          // m-splits (M-tile 128)
#define NTILES 8          // n-splits (N-tile 128)
#define CHUNKB 8192       // one chunk block: 128 rows x 64B (32 k-elems), SW64-swizzled
#define LSTRIDE (8 * CHUNKB)     // h-image: 8 chunks per lane
#define WNSTRIDE (16 * CHUNKB)   // w-image: 16 chunk slots per ntile
#define STAGEB 16384             // stage: A(8K) + W(8K)
#define NSTAGE 4
#define SMEM_DYN (NSTAGE * STAGEB + CHUNKB)  // + 8K h-staging = 73728

// ---------------- device scratch ----------------
__device__ float g_c1[BB * HH], g_c2[BB * HH];
__device__ __align__(128) char g_h1i[2][LANES * LSTRIDE];
__device__ __align__(128) char g_h2i[2][LANES * LSTRIDE];
__device__ __align__(128) char g_dini[LANES * LSTRIDE];
__device__ __align__(128) char g_ximg[(size_t)SS * LANES * 4 * CHUNKB];  // [t][lane][4 chunks]
__device__ __align__(128) char g_wimg[4][NTILES * WNSTRIDE];
__device__ float g_bias[4][GG];
__device__ float g_decout[(size_t)BB * SS * HH];
__device__ unsigned g_grpcnt[LANES];

struct CellDesc {
    const char* a1; const char* a2; const char* w;
    const float* bias; float* c; char* hout;
    long long a1_lstride; int nk1c; int tdec;
};
__device__ CellDesc g_desc[NCELLS];

// ---------------- helpers ----------------
__device__ __host__ __forceinline__ uint32_t swz64(uint32_t o) { return o ^ ((o >> 3) & 0x30); }

__device__ __forceinline__ uint32_t smem_u32(const void* p) {
    uint32_t a;
    asm("{ .reg .u64 t; cvta.to.shared.u64 t, %1; cvt.u32.u64 %0, t; }" : "=r"(a) : "l"(p));
    return a;
}
#define MBAR_INIT(a, c) asm volatile("mbarrier.init.shared.b64 [%0], %1;" :: "r"(a), "r"(c) : "memory")
#define MBAR_EXPECT(a, n) asm volatile("mbarrier.arrive.expect_tx.shared.b64 _, [%0], %1;" :: "r"(a), "r"(n) : "memory")
#define MBAR_WAIT(a, ph) do { \
    uint32_t _m = (a), _p = (ph), _d; \
    asm volatile("{\n\t.reg .pred p;\n\tmbarrier.try_wait.parity.acquire.cta.shared::cta.b64 p, [%1], %2;\n\tselp.b32 %0,1,0,p;\n\t}" \
        : "=r"(_d) : "r"(_m), "r"(_p) : "memory"); \
    if (!_d) { \
        asm volatile("{\n\t.reg .pred P1;\n\tWL_%=:\n\tmbarrier.try_wait.parity.acquire.cta.shared::cta.b64 P1, [%0], %1, 0x989680;\n\t@P1 bra.uni WD_%=;\n\tbra.uni WL_%=;\n\tWD_%=:\n\t}" \
            :: "r"(_m), "r"(_p) : "memory"); \
    } \
} while (0)
#define BULK_LD(sm, g, n, mb) \
    asm volatile("cp.async.bulk.shared::cta.global.mbarrier::complete_tx::bytes [%0], [%1], %2, [%3];" \
        :: "r"(sm), "l"(g), "r"(n), "r"(mb) : "memory")
#define BULK_ST(g, sm, n) \
    asm volatile("cp.async.bulk.global.shared::cta.bulk_group [%0], [%1], %2;" :: "l"(g), "r"(sm), "r"(n) : "memory")
#define BULK_COMMIT() asm volatile("cp.async.bulk.commit_group;" ::: "memory")
#define BULK_WAIT0()  asm volatile("cp.async.bulk.wait_group 0;" ::: "memory")
#define FENCE_ASYNC() asm volatile("fence.proxy.async.shared::cta;" ::: "memory")
#define LDSM4(r0, r1, r2, r3, a) \
    asm volatile("ldmatrix.sync.aligned.m8n8.x4.shared.b16 {%0,%1,%2,%3}, [%4];" \
        : "=r"(r0), "=r"(r1), "=r"(r2), "=r"(r3) : "r"(a))
#define MMA16816(d, a, b0, b1) \
    asm volatile("mma.sync.aligned.m16n8k16.row.col.f32.f16.f16.f32 " \
        "{%0,%1,%2,%3},{%4,%5,%6,%7},{%8,%9},{%0,%1,%2,%3};" \
        : "+f"((d)[0]), "+f"((d)[1]), "+f"((d)[2]), "+f"((d)[3]) \
        : "r"((a)[0]), "r"((a)[1]), "r"((a)[2]), "r"((a)[3]), "r"(b0), "r"(b1))
#define STS16(addr, v) asm volatile("st.shared.u16 [%0], %1;" :: "r"(addr), "h"(v) : "memory")

__device__ __forceinline__ float sigf(float x) { return __fdividef(1.f, 1.f + __expf(-x)); }
__device__ __forceinline__ float tanhv(float x) { return 2.f * sigf(2.f * x) - 1.f; }

// ---------------- setup kernels ----------------
// x -> swizzled image [t][lane][chunk(4)][128 rows x 64B]
__global__ void conv_x(const float* __restrict__ x) {
    int idx = blockIdx.x * 256 + threadIdx.x;     // one 16B unit (8 d-elems)
    if (idx >= BB * SS * 16) return;
    int ud = idx & 15, bt = idx >> 4;
    int t = bt & (SS - 1), b = bt >> 7;
    int d0 = ud * 8;
    const float4* src = (const float4*)(x + ((size_t)b * SS + t) * DD + d0);
    float4 v0 = src[0], v1 = src[1];
    uint32_t h01 = __halves2half2(__float2half_rn(v0.x), __float2half_rn(v0.y)).x ? 0 : 0; // placeholder avoid
    union { uint4 u; __half h[8]; } pk;
    pk.h[0] = __float2half_rn(v0.x); pk.h[1] = __float2half_rn(v0.y);
    pk.h[2] = __float2half_rn(v0.z); pk.h[3] = __float2half_rn(v0.w);
    pk.h[4] = __float2half_rn(v1.x); pk.h[5] = __float2half_rn(v1.y);
    pk.h[6] = __float2half_rn(v1.z); pk.h[7] = __float2half_rn(v1.w);
    int lane = b >> 7, rowl = b & 127, chunk = d0 >> 5;
    uint32_t colb = (uint32_t)(d0 & 31) * 2;
    char* dst = g_ximg + (((size_t)t * LANES + lane) * 4 + chunk) * CHUNKB
              + (uint32_t)rowl * 64 + (colb ^ (((uint32_t)rowl & 6) << 3));
    *(uint4*)dst = pk.u;
    (void)h01;
}

// weights -> swizzled images: [ws][ntile][chunk][128 n-rows x 64B]; chunks 0..nk1c-1 = Wih, rest = Whh
__global__ void setup_w(const float* wx0, const float* wh0, const float* wx1, const float* wh1,
                        const float* wx2, const float* wh2, const float* wx3, const float* wh3) {
    const int ws = blockIdx.y;
    int idx = blockIdx.x * 256 + threadIdx.x;           // unit: (ntile, c, row, u8)
    if (idx >= NTILES * 16 * 128 * 4) return;
    int u8 = idx & 3, r = (idx >> 2) & 127, c = (idx >> 9) & 15, ntile = idx >> 13;
    const int nk1c = (ws == 0) ? 4 : 8;
    const int K1 = (ws == 0) ? DD : HH;
    const float* wxs[4] = {wx0, wx1, wx2, wx3};
    const float* whs[4] = {wh0, wh1, wh2, wh3};
    const float* src; int K, k0;
    if (c < nk1c) { src = wxs[ws]; K = K1; k0 = c * 32 + u8 * 8; }
    else if (c < nk1c + 8) { src = whs[ws]; K = HH; k0 = (c - nk1c) * 32 + u8 * 8; }
    else return;                                        // unused slots (ws0 only)
    int nglob = ntile * 128 + r;
    int u = nglob >> 2, g = nglob & 3;
    const float4* s4 = (const float4*)(src + ((size_t)g * HH + u) * K + k0);
    float4 v0 = s4[0], v1 = s4[1];
    union { uint4 u4; __half h[8]; } pk;
    pk.h[0] = __float2half_rn(v0.x); pk.h[1] = __float2half_rn(v0.y);
    pk.h[2] = __float2half_rn(v0.z); pk.h[3] = __float2half_rn(v0.w);
    pk.h[4] = __float2half_rn(v1.x); pk.h[5] = __float2half_rn(v1.y);
    pk.h[6] = __float2half_rn(v1.z); pk.h[7] = __float2half_rn(v1.w);
    char* dst = g_wimg[ws] + (size_t)ntile * WNSTRIDE + (size_t)c * CHUNKB
              + (uint32_t)r * 64 + (((uint32_t)u8 * 16) ^ (((uint32_t)r & 6) << 3));
    *(uint4*)dst = pk.u4;
}

__global__ void setup_bias(const float* b0a, const float* b0b, const float* b1a, const float* b1b,
                           const float* b2a, const float* b2b, const float* b3a, const float* b3b) {
    int idx = blockIdx.x * 256 + threadIdx.x;
    if (idx >= 4 * GG) return;
    int ws = idx >> 10, r = idx & (GG - 1);
    const float* ba[4] = {b0a, b1a, b2a, b3a};
    const float* bb[4] = {b0b, b1b, b2b, b3b};
    int n = r >> 2, g = r & 3;
    g_bias[ws][r] = ba[ws][g * HH + n] + bb[ws][g * HH + n];
}

__global__ void zero_states() {
    int i = blockIdx.x * 256 + threadIdx.x;
    if (i < LANES) g_grpcnt[i] = 0u;
    uint4 z = {0, 0, 0, 0};
    if (i < 262144) {                       // 4 h-image buffers, 64K uint4 each
        int img = i >> 16, off = i & 65535;
        char* base = (img == 0) ? g_h1i[0] : (img == 1) ? g_h1i[1] : (img == 2) ? g_h2i[0] : g_h2i[1];
        ((uint4*)base)[off] = z;
    } else if (i < 524288) {
        int j = i - 262144;
        if (j < 131072) ((uint4*)g_c1)[j] = z;
        else ((uint4*)g_c2)[j - 131072] = z;
    }
}

__global__ void fill_desc() {
    int s = blockIdx.x * 256 + threadIdx.x;
    if (s >= NCELLS) return;
    CellDesc d; d.tdec = -1;
    if (s < 2 * SS) {
        int t = s >> 1, p = t & 1;
        if ((s & 1) == 0) {
            d.a1 = g_ximg + ((size_t)t * LANES * 4) * CHUNKB; d.a1_lstride = 4 * CHUNKB; d.nk1c = 4;
            d.a2 = g_h1i[p]; d.w = g_wimg[0]; d.bias = g_bias[0]; d.c = g_c1; d.hout = g_h1i[1 - p];
        } else {
            d.a1 = g_h1i[1 - p]; d.a1_lstride = LSTRIDE; d.nk1c = 8;
            d.a2 = g_h2i[p]; d.w = g_wimg[1]; d.bias = g_bias[1]; d.c = g_c2; d.hout = g_h2i[1 - p];
        }
    } else {
        int t = (s - 2 * SS) >> 1, p = t & 1;
        if ((s & 1) == 0) {
            d.a1 = (t == 0) ? g_dini : g_h2i[p]; d.a1_lstride = LSTRIDE; d.nk1c = 8;
            d.a2 = g_h1i[p]; d.w = g_wimg[2]; d.bias = g_bias[2]; d.c = g_c1; d.hout = g_h1i[1 - p];
        } else {
            d.a1 = g_h1i[1 - p]; d.a1_lstride = LSTRIDE; d.nk1c = 8;
            d.a2 = g_h2i[p]; d.w = g_wimg[3]; d.bias = g_bias[3]; d.c = g_c2; d.hout = g_h2i[1 - p];
            d.tdec = t;
        }
    }
    g_desc[s] = d;
}

// ---------------- per-m-lane barrier ----------------
__device__ __forceinline__ void lane_bar(int grp, unsigned target) {
    __syncthreads();
    if (threadIdx.x == 0) {
        __threadfence();
        atomicAdd(&g_grpcnt[grp], 1u);
        while (atomicAdd(&g_grpcnt[grp], 0u) < target) {}
        __threadfence();
    }
    __syncthreads();
}

// ---------------- persistent whole-recurrence kernel ----------------
__global__ __launch_bounds__(256, 1) void lstm_persist() {
    extern __shared__ __align__(128) char sm[];
    const uint32_t smu = smem_u32(sm);
    __shared__ __align__(8) uint64_t mbars[NSTAGE];

    const int tid = threadIdx.x;
    const int wl = tid & 31, wid = tid >> 5;
    const int ntile = blockIdx.x;         // 0..7
    const int mlane = blockIdx.y;         // 0..15
    const int m0 = mlane * 128;
    const int n0 = ntile * 128;
    const int wm = (wid & 3) * 32;
    const int wn = (wid >> 2) * 64;

    if (tid == 0)
        for (int i = 0; i < NSTAGE; i++) MBAR_INIT(smem_u32(&mbars[i]), 1);
    __syncthreads();

    // ldmatrix address components (swz64: addr = row*64 + (colb ^ ((row&6)<<3)))
    uint32_t aRow[2], aMask[2];
#pragma unroll
    for (int mt = 0; mt < 2; mt++) {
        uint32_t r = (uint32_t)(wm + mt * 16 + (wl & 15));
        aRow[mt] = r * 64; aMask[mt] = (r & 6) << 3;
    }
    const uint32_t aCol = (uint32_t)(wl >> 4) * 16;
    uint32_t wRow[4], wMask[4];
#pragma unroll
    for (int j2 = 0; j2 < 4; j2++) {
        uint32_t r = (uint32_t)(wn + (j2 * 2 + (wl >> 4)) * 8 + (wl & 7));
        wRow[j2] = r * 64; wMask[j2] = (r & 6) << 3;
    }
    const uint32_t wCol = (uint32_t)((wl >> 3) & 1) * 16;
    const uint32_t stg = smu + NSTAGE * STAGEB;   // 8KB h staging

    unsigned Gs = 0;      // cumulative stage counter (buffer/phase)
    unsigned epoch = 0;

    for (int s = 0; s < NCELLS; s++) {
        CellDesc d = g_desc[s];
        const char* a1 = d.a1 + (size_t)mlane * d.a1_lstride;
        const char* a2 = d.a2 + (size_t)mlane * LSTRIDE;
        const char* w = d.w + (size_t)ntile * WNSTRIDE;
        const int nk1c = d.nk1c;
        const int ns = nk1c + 8;

        float acc[2][8][4];
#pragma unroll
        for (int mt = 0; mt < 2; mt++)
#pragma unroll
            for (int j = 0; j < 8; j++)
#pragma unroll
                for (int r = 0; r < 4; r++) acc[mt][j][r] = 0.f;

        auto issue = [&](int c, unsigned gs) {
            if (tid == 0) {
                const int b = gs & 3;
                const uint32_t mb = smem_u32(&mbars[b]);
                const char* Ap = (c < nk1c) ? a1 + (size_t)c * CHUNKB
                                            : a2 + (size_t)(c - nk1c) * CHUNKB;
                const char* Wp = w + (size_t)c * CHUNKB;
                const uint32_t sA = smu + b * STAGEB;
                MBAR_EXPECT(mb, 16384);
                BULK_LD(sA, Ap, 8192, mb);
                BULK_LD(sA + 8192, Wp, 8192, mb);
            }
        };

        issue(0, Gs + 0); issue(1, Gs + 1); issue(2, Gs + 2);

        for (int sc = 0; sc < ns; sc++) {
            const unsigned gs = Gs + sc;
            const int b = gs & 3;
            MBAR_WAIT(smem_u32(&mbars[b]), (gs >> 2) & 1);
            const uint32_t base = smu + b * STAGEB;
#pragma unroll
            for (int ks = 0; ks < 2; ks++) {
                const uint32_t kb = (uint32_t)ks * 32;
                uint32_t a[2][4];
#pragma unroll
                for (int mt = 0; mt < 2; mt++)
                    LDSM4(a[mt][0], a[mt][1], a[mt][2], a[mt][3],
                          base + aRow[mt] + ((aCol + kb) ^ aMask[mt]));
                uint32_t wf[16];
#pragma unroll
                for (int j2 = 0; j2 < 4; j2++)
                    LDSM4(wf[4 * j2 + 0], wf[4 * j2 + 1], wf[4 * j2 + 2], wf[4 * j2 + 3],
                          base + 8192 + wRow[j2] + ((wCol + kb) ^ wMask[j2]));
#pragma unroll
                for (int mt = 0; mt < 2; mt++)
#pragma unroll
                    for (int j = 0; j < 8; j++)
                        MMA16816(acc[mt][j], a[mt], wf[2 * j], wf[2 * j + 1]);
            }
            __syncthreads();
            if (sc + 3 < ns) issue(sc + 3, Gs + sc + 3);
        }
        Gs += ns;

        // ---- epilogue: gates -> c (f32 STG), h -> smem staging (SW64 image) ----
        {
            const float* bias = d.bias;
            float* cbase = d.c;
            float* dbase = (d.tdec >= 0) ? g_decout + (size_t)d.tdec * HH : nullptr;
            const int q = wl & 3, p = q & 1, g = wl >> 2;
#pragma unroll
            for (int mt = 0; mt < 2; mt++) {
#pragma unroll
                for (int j = 0; j < 8; j++) {
                    float c0 = acc[mt][j][0], c1 = acc[mt][j][1];
                    float c2 = acc[mt][j][2], c3 = acc[mt][j][3];
                    float e0 = __shfl_xor_sync(0xffffffffu, c0, 1);
                    float e1 = __shfl_xor_sync(0xffffffffu, c1, 1);
                    float e2 = __shfl_xor_sync(0xffffffffu, c2, 1);
                    float e3 = __shfl_xor_sync(0xffffffffu, c3, 1);
                    const int rowl = wm + mt * 16 + g + (p ? 8 : 0);
                    const int row = m0 + rowl;
                    const int col = n0 + wn + j * 8 + (q >> 1) * 4;
                    float zi, zf, zg, zo;
                    if (!p) { zi = c0; zf = c1; zg = e0; zo = e1; }
                    else    { zi = e2; zf = e3; zg = c2; zo = c3; }
                    zi += bias[col];     zf += bias[col + 1];
                    zg += bias[col + 2]; zo += bias[col + 3];
                    const int un = col >> 2;
                    const size_t si = (size_t)row * HH + un;
                    float cold = cbase[si];
                    float ig = sigf(zi), fg = sigf(zf), og = sigf(zo);
                    float gt = tanhv(zg);
                    float cn = fg * cold + ig * gt;
                    float hn = og * tanhv(cn);
                    cbase[si] = cn;
                    const uint32_t ul = (uint32_t)((wn >> 2) + j * 2 + (q >> 1));
                    const uint32_t sa = stg + (uint32_t)rowl * 64
                                      + ((ul * 2) ^ (((uint32_t)rowl & 6) << 3));
                    STS16(sa, (unsigned short)__half_as_ushort(__float2half_rn(hn)));
                    if (dbase) dbase[(size_t)row * (SS * HH) + un] = hn;
                }
            }
        }
        __syncthreads();
        if (tid == 0) {
            FENCE_ASYNC();
            char* hg = d.hout + (size_t)mlane * LSTRIDE + (size_t)ntile * CHUNKB;
            BULK_ST(hg, stg, 8192);
            BULK_COMMIT();
            BULK_WAIT0();
        }
        lane_bar(mlane, 8u * (++epoch));

        if (s == 2 * SS - 1) {
            // encoder->decoder reset (each CTA handles its own blocks/slices)
            const size_t blk = (size_t)mlane * LSTRIDE + (size_t)ntile * CHUNKB;
            const uint4* srcB = (const uint4*)(g_h2i[0] + blk);
            uint4* dinB = (uint4*)(g_dini + blk);
            for (int i = tid; i < 512; i += 256) dinB[i] = srcB[i];
            uint4 z = {0, 0, 0, 0};
            uint4* zb[4] = {(uint4*)(g_h1i[0] + blk), (uint4*)(g_h1i[1] + blk),
                            (uint4*)(g_h2i[0] + blk), (uint4*)(g_h2i[1] + blk)};
#pragma unroll
            for (int v = 0; v < 4; v++)
                for (int i = tid; i < 512; i += 256) zb[v][i] = z;
            const int un0 = ntile * 32;
            for (int i = tid; i < 128 * 32; i += 256) {
                const int r = m0 + (i >> 5);
                const int u = un0 + (i & 31);
                g_c1[(size_t)r * HH + u] = 0.f;
                g_c2[(size_t)r * HH + u] = 0.f;
            }
            lane_bar(mlane, 8u * (++epoch));
        }
    }
}

// ---------------- output projection (f32 SIMT, reads g_decout) ----------------
__global__ __launch_bounds__(256, 1)
void out_proj(const float* __restrict__ W, const float* __restrict__ bout,
              float* __restrict__ out) {
    __shared__ float As[2][16][132];
    __shared__ float Bs[2][16][132];
    const int tid = threadIdx.x;
    const int tx = tid & 15, ty = tid >> 4;
    const int m0 = blockIdx.y * 128;
    const int arow = tid >> 1;
    const int acol = (tid & 1) << 3;
    const int ntiles = HH >> 4;

    const float* a0row = g_decout + (size_t)(m0 + arow) * HH + acol;
    const float* w0row = W + (size_t)arow * HH + acol;

    float acc[8][8];
#pragma unroll
    for (int i = 0; i < 8; i++)
#pragma unroll
        for (int j = 0; j < 8; j++) acc[i][j] = 0.f;
    {
        float4 ra0 = *(const float4*)a0row;
        float4 ra1 = *(const float4*)(a0row + 4);
        float4 rb0 = *(const float4*)w0row;
        float4 rb1 = *(const float4*)(w0row + 4);
        float* sa = &As[0][acol][arow];
        float* sb = &Bs[0][acol][arow];
        sa[0*132]=ra0.x; sa[1*132]=ra0.y; sa[2*132]=ra0.z; sa[3*132]=ra0.w;
        sa[4*132]=ra1.x; sa[5*132]=ra1.y; sa[6*132]=ra1.z; sa[7*132]=ra1.w;
        sb[0*132]=rb0.x; sb[1*132]=rb0.y; sb[2*132]=rb0.z; sb[3*132]=rb0.w;
        sb[4*132]=rb1.x; sb[5*132]=rb1.y; sb[6*132]=rb1.z; sb[7*132]=rb1.w;
    }
    __syncthreads();
    for (int t = 0; t < ntiles; t++) {
        const int cur = t & 1;
        const bool more = (t + 1 < ntiles);
        float4 ra0, ra1, rb0, rb1;
        if (more) {
            const float* ap = a0row + (t + 1) * 16;
            const float* wp = w0row + (t + 1) * 16;
            ra0 = *(const float4*)ap; ra1 = *(const float4*)(ap + 4);
            rb0 = *(const float4*)wp; rb1 = *(const float4*)(wp + 4);
        }
#pragma unroll
        for (int k = 0; k < 16; k++) {
            const float* as = &As[cur][k][0];
            const float* bs = &Bs[cur][k][0];
            float4 a0 = *(const float4*)(as + ty * 8);
            float4 a1 = *(const float4*)(as + ty * 8 + 4);
            float4 b0 = *(const float4*)(bs + tx * 8);
            float4 b1 = *(const float4*)(bs + tx * 8 + 4);
            float av[8] = {a0.x, a0.y, a0.z, a0.w, a1.x, a1.y, a1.z, a1.w};
            float bv[8] = {b0.x, b0.y, b0.z, b0.w, b1.x, b1.y, b1.z, b1.w};
#pragma unroll
            for (int i = 0; i < 8; i++)
#pragma unroll
                for (int j = 0; j < 8; j++) acc[i][j] += av[i] * bv[j];
        }
        if (more) {
            const int nxt = cur ^ 1;
            float* sa = &As[nxt][acol][arow];
            float* sb = &Bs[nxt][acol][arow];
            sa[0*132]=ra0.x; sa[1*132]=ra0.y; sa[2*132]=ra0.z; sa[3*132]=ra0.w;
            sa[4*132]=ra1.x; sa[5*132]=ra1.y; sa[6*132]=ra1.z; sa[7*132]=ra1.w;
            sb[0*132]=rb0.x; sb[1*132]=rb0.y; sb[2*132]=rb0.z; sb[3*132]=rb0.w;
            sb[4*132]=rb1.x; sb[5*132]=rb1.y; sb[6*132]=rb1.z; sb[7*132]=rb1.w;
        }
        __syncthreads();
    }
#pragma unroll
    for (int i = 0; i < 8; i++) {
        const int m = m0 + ty * 8 + i;
#pragma unroll
        for (int j = 0; j < 8; j++) {
            const int col = tx * 8 + j;
            out[(size_t)m * DD + col] = acc[i][j] + bout[col];
        }
    }
}

// ---------------- host-side orchestration ----------------
extern "C" void kernel_launch(void* const* d_in, const int* in_sizes, int n_in,
                              void* d_out, int out_size) {
    (void)in_sizes; (void)n_in; (void)out_size;
    const float* x = (const float*)d_in[0];

    cudaFuncSetAttribute(lstm_persist, cudaFuncAttributeMaxDynamicSharedMemorySize, SMEM_DYN);

    conv_x<<<(BB * SS * 16 + 255) / 256, 256>>>(x);
    setup_w<<<dim3(NTILES * 16 * 128 * 4 / 256, 4), 256>>>(
        (const float*)d_in[1], (const float*)d_in[2],
        (const float*)d_in[5], (const float*)d_in[6],
        (const float*)d_in[9], (const float*)d_in[10],
        (const float*)d_in[13], (const float*)d_in[14]);
    setup_bias<<<(4 * GG + 255) / 256, 256>>>(
        (const float*)d_in[3], (const float*)d_in[4],
        (const float*)d_in[7], (const float*)d_in[8],
        (const float*)d_in[11], (const float*)d_in[12],
        (const float*)d_in[15], (const float*)d_in[16]);
    zero_states<<<2048, 256>>>();
    fill_desc<<<2, 256>>>();

    lstm_persist<<<dim3(NTILES, LANES), 256, SMEM_DYN>>>();

    out_proj<<<dim3(1, (BB * SS) / 128), 256>>>((const float*)d_in[17],
                                                (const float*)d_in[18],
                                                (float*)d_out);
}

// round 10
// speedup vs baseline: 1.6191x; 1.0683x over previous
#include <cuda_runtime.h>
#include <cuda_fp16.h>
#include <stdint.h>

#define BB 2048
#define SS 128
#define DD 128
#define HH 256
#define GG 1024
#define NCELLS 512
#define LANES 16
#define NTILES 8
#define CHUNKA 8192            // A k32 sub-chunk: 128 rows x 64B, SW64
#define CHUNKW 16384           // W k64 chunk: 128 rows x 128B, SW128
#define LSTRIDE (8 * CHUNKA)   // h-image per lane (K=256)
#define XSTRIDE (4 * CHUNKA)   // x-image per (t,lane) (K=128)
#define WNSTRIDE (8 * CHUNKW)  // w-image per ntile: slots [Wih(2|4) | Whh(4)]
#define STAGEB 32768           // stage: A 16KB + W 16KB
#define NSTAGE 4
#define SMEM_DYN (NSTAGE * STAGEB + CHUNKA)  // +8KB h staging = 139264

// ---------------- device scratch ----------------
__device__ float g_c1[BB * HH], g_c2[BB * HH];
__device__ __align__(128) char g_h1i[2][LANES * LSTRIDE];
__device__ __align__(128) char g_h2i[2][LANES * LSTRIDE];
__device__ __align__(128) char g_dini[LANES * LSTRIDE];
__device__ __align__(128) char g_ximg[(size_t)SS * LANES * XSTRIDE];
__device__ __align__(128) char g_wimg[4][NTILES * WNSTRIDE];
__device__ float g_bias[4][GG];
__device__ float g_decout[(size_t)BB * SS * HH];
__device__ unsigned g_grpcnt[LANES];

struct CellDesc {
    const char* a1; const char* a2; const char* w;
    const float* bias; float* c; char* hout;
    int a1_lstride; int nA1st; int tdec;
};
__device__ CellDesc g_desc[NCELLS];

// ---------------- helpers ----------------
__device__ __forceinline__ uint32_t smem_u32(const void* p) {
    uint32_t a;
    asm("{ .reg .u64 t; cvta.to.shared.u64 t, %1; cvt.u32.u64 %0, t; }" : "=r"(a) : "l"(p));
    return a;
}
#define MBAR_INIT(a, c) asm volatile("mbarrier.init.shared.b64 [%0], %1;" :: "r"(a), "r"(c) : "memory")
#define MBAR_EXPECT(a, n) asm volatile("mbarrier.arrive.expect_tx.shared.b64 _, [%0], %1;" :: "r"(a), "r"(n) : "memory")
#define MBAR_WAIT(a, ph) do { \
    uint32_t _m = (a), _p = (ph), _d; \
    asm volatile("{\n\t.reg .pred p;\n\tmbarrier.try_wait.parity.acquire.cta.shared::cta.b64 p, [%1], %2;\n\tselp.b32 %0,1,0,p;\n\t}" \
        : "=r"(_d) : "r"(_m), "r"(_p) : "memory"); \
    if (!_d) { \
        asm volatile("{\n\t.reg .pred P1;\n\tWL_%=:\n\tmbarrier.try_wait.parity.acquire.cta.shared::cta.b64 P1, [%0], %1, 0x989680;\n\t@P1 bra.uni WD_%=;\n\tbra.uni WL_%=;\n\tWD_%=:\n\t}" \
            :: "r"(_m), "r"(_p) : "memory"); \
    } \
} while (0)
#define BULK_LD(sm, g, n, mb) \
    asm volatile("cp.async.bulk.shared::cta.global.mbarrier::complete_tx::bytes [%0], [%1], %2, [%3];" \
        :: "r"(sm), "l"(g), "r"(n), "r"(mb) : "memory")
#define BULK_ST(g, sm, n) \
    asm volatile("cp.async.bulk.global.shared::cta.bulk_group [%0], [%1], %2;" :: "l"(g), "r"(sm), "r"(n) : "memory")
#define BULK_COMMIT() asm volatile("cp.async.bulk.commit_group;" ::: "memory")
#define BULK_WAIT0()  asm volatile("cp.async.bulk.wait_group 0;" ::: "memory")
#define FENCE_ASYNC() asm volatile("fence.proxy.async.shared::cta;" ::: "memory")
#define LDSM4(r0, r1, r2, r3, a) \
    asm volatile("ldmatrix.sync.aligned.m8n8.x4.shared.b16 {%0,%1,%2,%3}, [%4];" \
        : "=r"(r0), "=r"(r1), "=r"(r2), "=r"(r3) : "r"(a))
#define MMA16816(d, a, b0, b1) \
    asm volatile("mma.sync.aligned.m16n8k16.row.col.f32.f16.f16.f32 " \
        "{%0,%1,%2,%3},{%4,%5,%6,%7},{%8,%9},{%0,%1,%2,%3};" \
        : "+f"((d)[0]), "+f"((d)[1]), "+f"((d)[2]), "+f"((d)[3]) \
        : "r"((a)[0]), "r"((a)[1]), "r"((a)[2]), "r"((a)[3]), "r"(b0), "r"(b1))
#define STS16(addr, v) asm volatile("st.shared.u16 [%0], %1;" :: "r"(addr), "h"(v) : "memory")

__device__ __forceinline__ float sigf(float x) { return __fdividef(1.f, 1.f + __expf(-x)); }
__device__ __forceinline__ float tanhv(float x) { return 2.f * sigf(2.f * x) - 1.f; }

// ---------------- launch 1: x -> SW64 image ----------------
__global__ void conv_x(const float* __restrict__ x) {
    int idx = blockIdx.x * 256 + threadIdx.x;
    if (idx >= BB * SS * 16) return;
    int ud = idx & 15, bt = idx >> 4;
    int t = bt & (SS - 1), b = bt >> 7;
    int d0 = ud * 8;
    const float4* src = (const float4*)(x + ((size_t)b * SS + t) * DD + d0);
    float4 v0 = src[0], v1 = src[1];
    union { uint4 u; __half h[8]; } pk;
    pk.h[0] = __float2half_rn(v0.x); pk.h[1] = __float2half_rn(v0.y);
    pk.h[2] = __float2half_rn(v0.z); pk.h[3] = __float2half_rn(v0.w);
    pk.h[4] = __float2half_rn(v1.x); pk.h[5] = __float2half_rn(v1.y);
    pk.h[6] = __float2half_rn(v1.z); pk.h[7] = __float2half_rn(v1.w);
    int lane = b >> 7, rowl = b & 127, chunk = d0 >> 5;
    uint32_t colb = (uint32_t)(d0 & 31) * 2;
    char* dst = g_ximg + ((size_t)t * LANES + lane) * XSTRIDE + (size_t)chunk * CHUNKA
              + (uint32_t)rowl * 64 + (colb ^ (((uint32_t)rowl & 6) << 3));
    *(uint4*)dst = pk.u;
}

// ---------------- launch 2: weights (y=0..3, Wih-first slots) + bias (y=4) ----------------
__global__ void setup_wb(const float* wx0, const float* wh0, const float* wx1, const float* wh1,
                         const float* wx2, const float* wh2, const float* wx3, const float* wh3,
                         const float* b0a, const float* b0b, const float* b1a, const float* b1b,
                         const float* b2a, const float* b2b, const float* b3a, const float* b3b) {
    const int y = blockIdx.y;
    int idx = blockIdx.x * 256 + threadIdx.x;
    if (y == 4) {
        if (idx >= 4 * GG) return;
        int ws = idx >> 10, r = idx & (GG - 1);
        const float* ba[4] = {b0a, b1a, b2a, b3a};
        const float* bb[4] = {b0b, b1b, b2b, b3b};
        int n = r >> 2, g = r & 3;
        g_bias[ws][r] = ba[ws][g * HH + n] + bb[ws][g * HH + n];
        return;
    }
    const int ws = y;
    if (idx >= 65536) return;
    int u8 = idx & 7, r = (idx >> 3) & 127, c = (idx >> 10) & 7, ntile = idx >> 13;
    const int nk1c = (ws == 0) ? 2 : 4;
    const int K1 = (ws == 0) ? DD : HH;
    const float* wxs[4] = {wx0, wx1, wx2, wx3};
    const float* whs[4] = {wh0, wh1, wh2, wh3};
    const float* src; int K, k0;
    if (c < nk1c) { src = wxs[ws]; K = K1; k0 = c * 64 + u8 * 8; }
    else if (c < nk1c + 4) { src = whs[ws]; K = HH; k0 = (c - nk1c) * 64 + u8 * 8; }
    else return;
    int nglob = ntile * 128 + r;
    int u = nglob >> 2, g = nglob & 3;
    const float4* s4 = (const float4*)(src + ((size_t)g * HH + u) * K + k0);
    float4 v0 = s4[0], v1 = s4[1];
    union { uint4 u4; __half h[8]; } pk;
    pk.h[0] = __float2half_rn(v0.x); pk.h[1] = __float2half_rn(v0.y);
    pk.h[2] = __float2half_rn(v0.z); pk.h[3] = __float2half_rn(v0.w);
    pk.h[4] = __float2half_rn(v1.x); pk.h[5] = __float2half_rn(v1.y);
    pk.h[6] = __float2half_rn(v1.z); pk.h[7] = __float2half_rn(v1.w);
    char* dst = g_wimg[ws] + (size_t)ntile * WNSTRIDE + (size_t)c * CHUNKW
              + (uint32_t)r * 128 + (((uint32_t)u8 * 16) ^ (((uint32_t)r & 7) << 4));
    *(uint4*)dst = pk.u4;
}

// ---------------- launch 3: zero states + fill descriptors ----------------
__global__ void zero_fill() {
    if (blockIdx.x >= 2048) {
        int s = (blockIdx.x - 2048) * 256 + threadIdx.x;
        if (s >= NCELLS) return;
        CellDesc d; d.tdec = -1;
        if (s < 2 * SS) {
            int t = s >> 1, p = t & 1;
            if ((s & 1) == 0) {
                d.a1 = g_ximg + (size_t)t * LANES * XSTRIDE; d.a1_lstride = XSTRIDE; d.nA1st = 2;
                d.a2 = g_h1i[p]; d.w = g_wimg[0]; d.bias = g_bias[0]; d.c = g_c1; d.hout = g_h1i[1 - p];
            } else {
                d.a1 = g_h1i[1 - p]; d.a1_lstride = LSTRIDE; d.nA1st = 4;
                d.a2 = g_h2i[p]; d.w = g_wimg[1]; d.bias = g_bias[1]; d.c = g_c2; d.hout = g_h2i[1 - p];
            }
        } else {
            int t = (s - 2 * SS) >> 1, p = t & 1;
            if ((s & 1) == 0) {
                d.a1 = (t == 0) ? g_dini : g_h2i[p]; d.a1_lstride = LSTRIDE; d.nA1st = 4;
                d.a2 = g_h1i[p]; d.w = g_wimg[2]; d.bias = g_bias[2]; d.c = g_c1; d.hout = g_h1i[1 - p];
            } else {
                d.a1 = g_h1i[1 - p]; d.a1_lstride = LSTRIDE; d.nA1st = 4;
                d.a2 = g_h2i[p]; d.w = g_wimg[3]; d.bias = g_bias[3]; d.c = g_c2; d.hout = g_h2i[1 - p];
                d.tdec = t;
            }
        }
        g_desc[s] = d;
        return;
    }
    int i = blockIdx.x * 256 + threadIdx.x;
    if (i < LANES) g_grpcnt[i] = 0u;
    uint4 z = {0, 0, 0, 0};
    if (i < 262144) {
        int img = i >> 16, off = i & 65535;
        char* base = (img == 0) ? g_h1i[0] : (img == 1) ? g_h1i[1] : (img == 2) ? g_h2i[0] : g_h2i[1];
        ((uint4*)base)[off] = z;
    } else {
        int j = i - 262144;
        if (j < 131072) ((uint4*)g_c1)[j] = z;
        else ((uint4*)g_c2)[j - 131072] = z;
    }
}

// ---------------- per-m-lane barrier (R8-proven) ----------------
__device__ __forceinline__ void lane_bar(int grp, unsigned target) {
    __syncthreads();
    if (threadIdx.x == 0) {
        __threadfence();
        atomicAdd(&g_grpcnt[grp], 1u);
        while (atomicAdd(&g_grpcnt[grp], 0u) < target) {}
        __threadfence();
    }
    __syncthreads();
}

// ---------------- launch 4: persistent recurrence ----------------
__global__ __launch_bounds__(256, 1) void lstm_persist() {
    extern __shared__ __align__(128) char sm[];
    const uint32_t smu = smem_u32(sm);
    __shared__ __align__(8) uint64_t mbars[NSTAGE];

    const int tid = threadIdx.x;
    const int wl = tid & 31, wid = tid >> 5;
    const int ntile = blockIdx.x;
    const int mlane = blockIdx.y;
    const int m0 = mlane * 128;
    const int n0 = ntile * 128;
    const int wm = (wid & 3) * 32;
    const int wn = (wid >> 2) * 64;

    if (tid == 0)
        for (int i = 0; i < NSTAGE; i++) MBAR_INIT(smem_u32(&mbars[i]), 1);
    __syncthreads();

    // A (SW64, 64B rows)
    uint32_t aRow[2], aMask[2];
#pragma unroll
    for (int mt = 0; mt < 2; mt++) {
        uint32_t r = (uint32_t)(wm + mt * 16 + (wl & 15));
        aRow[mt] = r * 64; aMask[mt] = (r & 6) << 3;
    }
    const uint32_t aCol = (uint32_t)(wl >> 4) * 16;
    // W (SW128, 128B rows)
    uint32_t wRow[4], wMask[4];
#pragma unroll
    for (int j2 = 0; j2 < 4; j2++) {
        uint32_t r = (uint32_t)(wn + (j2 * 2 + (wl >> 4)) * 8 + (wl & 7));
        wRow[j2] = r * 128; wMask[j2] = (r & 7) << 4;
    }
    const uint32_t wCol = (uint32_t)((wl >> 3) & 1) * 16;
    const uint32_t stg = smu + NSTAGE * STAGEB;

    unsigned Gs = 0, epoch = 0;

    for (int s = 0; s < NCELLS; s++) {
        CellDesc d = g_desc[s];
        const int ns = d.nA1st + 4;

        float acc[2][8][4];
#pragma unroll
        for (int mt = 0; mt < 2; mt++)
#pragma unroll
            for (int j = 0; j < 8; j++)
#pragma unroll
                for (int r = 0; r < 4; r++) acc[mt][j][r] = 0.f;

        auto issue = [&](int c, unsigned gs) {
            if (tid == 0) {
                const int b = gs & 3;
                const uint32_t mb = smem_u32(&mbars[b]);
                const char* A = (c < d.nA1st)
                    ? d.a1 + (size_t)mlane * d.a1_lstride + (size_t)c * (2 * CHUNKA)
                    : d.a2 + (size_t)mlane * LSTRIDE + (size_t)(c - d.nA1st) * (2 * CHUNKA);
                const char* W = d.w + (size_t)ntile * WNSTRIDE + (size_t)c * CHUNKW;
                const uint32_t sb = smu + b * STAGEB;
                MBAR_EXPECT(mb, 32768);
                BULK_LD(sb, A, 16384, mb);
                BULK_LD(sb + 16384, W, 16384, mb);
            }
        };

        issue(0, Gs + 0); issue(1, Gs + 1); issue(2, Gs + 2);

        for (int sc = 0; sc < ns; sc++) {
            const unsigned gs = Gs + sc;
            const int b = gs & 3;
            MBAR_WAIT(smem_u32(&mbars[b]), (gs >> 2) & 1);
            const uint32_t base = smu + b * STAGEB;
#pragma unroll
            for (int ks = 0; ks < 4; ks++) {
                const uint32_t asub = (uint32_t)(ks >> 1) * 8192;
                const uint32_t akb = (uint32_t)(ks & 1) * 32;
                uint32_t a[2][4];
#pragma unroll
                for (int mt = 0; mt < 2; mt++)
                    LDSM4(a[mt][0], a[mt][1], a[mt][2], a[mt][3],
                          base + asub + aRow[mt] + ((aCol + akb) ^ aMask[mt]));
                uint32_t wf[16];
#pragma unroll
                for (int j2 = 0; j2 < 4; j2++)
                    LDSM4(wf[4 * j2 + 0], wf[4 * j2 + 1], wf[4 * j2 + 2], wf[4 * j2 + 3],
                          base + 16384 + wRow[j2] + ((wCol + (uint32_t)ks * 32) ^ wMask[j2]));
#pragma unroll
                for (int mt = 0; mt < 2; mt++)
#pragma unroll
                    for (int j = 0; j < 8; j++)
                        MMA16816(acc[mt][j], a[mt], wf[2 * j], wf[2 * j + 1]);
            }
            __syncthreads();
            if (sc + 3 < ns) issue(sc + 3, gs + 3);
        }
        Gs += ns;

        // ---- epilogue: gates -> c, h -> SW64 staging, decout f32 ----
        {
            const float* bias = d.bias;
            float* cbase = d.c;
            float* dbase = (d.tdec >= 0) ? g_decout + (size_t)d.tdec * HH : nullptr;
            const int q = wl & 3, p = q & 1, g = wl >> 2;
#pragma unroll
            for (int mt = 0; mt < 2; mt++) {
#pragma unroll
                for (int j = 0; j < 8; j++) {
                    float c0 = acc[mt][j][0], c1 = acc[mt][j][1];
                    float c2 = acc[mt][j][2], c3 = acc[mt][j][3];
                    float e0 = __shfl_xor_sync(0xffffffffu, c0, 1);
                    float e1 = __shfl_xor_sync(0xffffffffu, c1, 1);
                    float e2 = __shfl_xor_sync(0xffffffffu, c2, 1);
                    float e3 = __shfl_xor_sync(0xffffffffu, c3, 1);
                    const int rowl = wm + mt * 16 + g + (p ? 8 : 0);
                    const int row = m0 + rowl;
                    const int col = n0 + wn + j * 8 + (q >> 1) * 4;
                    float zi, zf, zg, zo;
                    if (!p) { zi = c0; zf = c1; zg = e0; zo = e1; }
                    else    { zi = e2; zf = e3; zg = c2; zo = c3; }
                    zi += bias[col];     zf += bias[col + 1];
                    zg += bias[col + 2]; zo += bias[col + 3];
                    const int un = col >> 2;
                    const size_t si = (size_t)row * HH + un;
                    float cold = cbase[si];
                    float ig = sigf(zi), fg = sigf(zf), og = sigf(zo);
                    float gt = tanhv(zg);
                    float cn = fg * cold + ig * gt;
                    float hn = og * tanhv(cn);
                    cbase[si] = cn;
                    const uint32_t ul = (uint32_t)((wn >> 2) + j * 2 + (q >> 1));
                    const uint32_t sa = stg + (uint32_t)rowl * 64
                                      + ((ul * 2) ^ (((uint32_t)rowl & 6) << 3));
                    STS16(sa, (unsigned short)__half_as_ushort(__float2half_rn(hn)));
                    if (dbase) dbase[(size_t)row * (SS * HH) + un] = hn;
                }
            }
        }
        __syncthreads();
        if (tid == 0) {
            FENCE_ASYNC();
            char* hg = d.hout + (size_t)mlane * LSTRIDE + (size_t)ntile * CHUNKA;
            BULK_ST(hg, stg, 8192);
            BULK_COMMIT();
            BULK_WAIT0();
        }
        lane_bar(mlane, 8u * (++epoch));

        if (s == 2 * SS - 1) {
            const size_t blk = (size_t)mlane * LSTRIDE + (size_t)ntile * CHUNKA;
            const uint4* srcB = (const uint4*)(g_h2i[0] + blk);
            uint4* dinB = (uint4*)(g_dini + blk);
            for (int i = tid; i < 512; i += 256) dinB[i] = srcB[i];
            uint4 z = {0, 0, 0, 0};
            uint4* zb[4] = {(uint4*)(g_h1i[0] + blk), (uint4*)(g_h1i[1] + blk),
                            (uint4*)(g_h2i[0] + blk), (uint4*)(g_h2i[1] + blk)};
#pragma unroll
            for (int v = 0; v < 4; v++)
                for (int i = tid; i < 512; i += 256) zb[v][i] = z;
            const int un0 = ntile * 32;
            for (int i = tid; i < 128 * 32; i += 256) {
                const int r = m0 + (i >> 5);
                const int u = un0 + (i & 31);
                g_c1[(size_t)r * HH + u] = 0.f;
                g_c2[(size_t)r * HH + u] = 0.f;
            }
            lane_bar(mlane, 8u * (++epoch));
        }
    }
}

// ---------------- launch 5: output projection ----------------
__global__ __launch_bounds__(256, 1)
void out_proj(const float* __restrict__ W, const float* __restrict__ bout,
              float* __restrict__ out) {
    __shared__ float As[2][16][132];
    __shared__ float Bs[2][16][132];
    const int tid = threadIdx.x;
    const int tx = tid & 15, ty = tid >> 4;
    const int m0 = blockIdx.y * 128;
    const int arow = tid >> 1;
    const int acol = (tid & 1) << 3;
    const int ntiles = HH >> 4;

    const float* a0row = g_decout + (size_t)(m0 + arow) * HH + acol;
    const float* w0row = W + (size_t)arow * HH + acol;

    float acc[8][8];
#pragma unroll
    for (int i = 0; i < 8; i++)
#pragma unroll
        for (int j = 0; j < 8; j++) acc[i][j] = 0.f;
    {
        float4 ra0 = *(const float4*)a0row;
        float4 ra1 = *(const float4*)(a0row + 4);
        float4 rb0 = *(const float4*)w0row;
        float4 rb1 = *(const float4*)(w0row + 4);
        float* sa = &As[0][acol][arow];
        float* sb = &Bs[0][acol][arow];
        sa[0*132]=ra0.x; sa[1*132]=ra0.y; sa[2*132]=ra0.z; sa[3*132]=ra0.w;
        sa[4*132]=ra1.x; sa[5*132]=ra1.y; sa[6*132]=ra1.z; sa[7*132]=ra1.w;
        sb[0*132]=rb0.x; sb[1*132]=rb0.y; sb[2*132]=rb0.z; sb[3*132]=rb0.w;
        sb[4*132]=rb1.x; sb[5*132]=rb1.y; sb[6*132]=rb1.z; sb[7*132]=rb1.w;
    }
    __syncthreads();
    for (int t = 0; t < ntiles; t++) {
        const int cur = t & 1;
        const bool more = (t + 1 < ntiles);
        float4 ra0, ra1, rb0, rb1;
        if (more) {
            const float* ap = a0row + (t + 1) * 16;
            const float* wp = w0row + (t + 1) * 16;
            ra0 = *(const float4*)ap; ra1 = *(const float4*)(ap + 4);
            rb0 = *(const float4*)wp; rb1 = *(const float4*)(wp + 4);
        }
#pragma unroll
        for (int k = 0; k < 16; k++) {
            const float* as = &As[cur][k][0];
            const float* bs = &Bs[cur][k][0];
            float4 a0 = *(const float4*)(as + ty * 8);
            float4 a1 = *(const float4*)(as + ty * 8 + 4);
            float4 b0 = *(const float4*)(bs + tx * 8);
            float4 b1 = *(const float4*)(bs + tx * 8 + 4);
            float av[8] = {a0.x, a0.y, a0.z, a0.w, a1.x, a1.y, a1.z, a1.w};
            float bv[8] = {b0.x, b0.y, b0.z, b0.w, b1.x, b1.y, b1.z, b1.w};
#pragma unroll
            for (int i = 0; i < 8; i++)
#pragma unroll
                for (int j = 0; j < 8; j++) acc[i][j] += av[i] * bv[j];
        }
        if (more) {
            const int nxt = cur ^ 1;
            float* sa = &As[nxt][acol][arow];
            float* sb = &Bs[nxt][acol][arow];
            sa[0*132]=ra0.x; sa[1*132]=ra0.y; sa[2*132]=ra0.z; sa[3*132]=ra0.w;
            sa[4*132]=ra1.x; sa[5*132]=ra1.y; sa[6*132]=ra1.z; sa[7*132]=ra1.w;
            sb[0*132]=rb0.x; sb[1*132]=rb0.y; sb[2*132]=rb0.z; sb[3*132]=rb0.w;
            sb[4*132]=rb1.x; sb[5*132]=rb1.y; sb[6*132]=rb1.z; sb[7*132]=rb1.w;
        }
        __syncthreads();
    }
#pragma unroll
    for (int i = 0; i < 8; i++) {
        const int m = m0 + ty * 8 + i;
#pragma unroll
        for (int j = 0; j < 8; j++) {
            const int col = tx * 8 + j;
            out[(size_t)m * DD + col] = acc[i][j] + bout[col];
        }
    }
}

// ---------------- host ----------------
extern "C" void kernel_launch(void* const* d_in, const int* in_sizes, int n_in,
                              void* d_out, int out_size) {
    (void)in_sizes; (void)n_in; (void)out_size;
    const float* x = (const float*)d_in[0];

    cudaFuncSetAttribute(lstm_persist, cudaFuncAttributeMaxDynamicSharedMemorySize, SMEM_DYN);

    conv_x<<<(BB * SS * 16 + 255) / 256, 256>>>(x);                         // launch 1
    setup_wb<<<dim3(256, 5), 256>>>(                                        // launch 2
        (const float*)d_in[1], (const float*)d_in[2],
        (const float*)d_in[5], (const float*)d_in[6],
        (const float*)d_in[9], (const float*)d_in[10],
        (const float*)d_in[13], (const float*)d_in[14],
        (const float*)d_in[3], (const float*)d_in[4],
        (const float*)d_in[7], (const float*)d_in[8],
        (const float*)d_in[11], (const float*)d_in[12],
        (const float*)d_in[15], (const float*)d_in[16]);
    zero_fill<<<2050, 256>>>();                                             // launch 3
    lstm_persist<<<dim3(NTILES, LANES), 256, SMEM_DYN>>>();                 // launch 4 (ncu)
    out_proj<<<dim3(1, (BB * SS) / 128), 256>>>((const float*)d_in[17],     // launch 5
                                                (const float*)d_in[18],
                                                (float*)d_out);
}